// round 15
// baseline (speedup 1.0000x reference)
#include <cuda_runtime.h>
#include <cuda_fp16.h>
#include <cstdint>

#define NB    4
#define NC    64
#define NHEAD 8
#define HD    8
#define NWID  128
#define NH    128
#define HWSZ  (NH*NWID)
#define NWIN  64
#define NTOK  256
#define VPAD  264
#define PSTR  65
#define PRE_CTAS (NB*3*NHEAD*16)    // 1536 prepass shards (8 rows each)
#define ATT_CTAS (NB*NHEAD*32)      // 1024 attention CTAs

typedef uint32_t u32;

// window-major staging (f16): Qg/Kg = [B][head][win][tok][d], Vg = [B][head][win][d][tok]
__device__ __half Qg[(size_t)NB*NHEAD*NWIN*NTOK*HD];
__device__ __half Kg[(size_t)NB*NHEAD*NWIN*NTOK*HD];
__device__ __half Vg[(size_t)NB*NHEAD*NWIN*HD*NTOK];
__device__ unsigned int cnt_g[NB*NHEAD];    // prepass completion count (reset by consumers)
__device__ unsigned int done_g[NB*NHEAD];   // attention consumption count

struct AttnSmem {
    __half Ksm[2 * NTOK][HD];              // 8 KB
    char   qo[2 * NTOK * 12 * 2];          // 12 KB: Qsm then Osm
    __half Vt[2][HD][VPAD];                // 8.25 KB
    float  Wc[HD][9];
    float  Bc[HD];
};
struct PreSmem { __half Ss[128 * PSTR]; }; // 16.6 KB

__device__ __forceinline__ u32 cvt2h(float lo, float hi) {
    u32 r; asm("cvt.rn.f16x2.f32 %0, %1, %2;" : "=r"(r) : "f"(hi), "f"(lo)); return r;
}
__device__ __forceinline__ u32 hex2(u32 x) {
    u32 r; asm("ex2.approx.f16x2 %0, %1;" : "=r"(r) : "r"(x)); return r;
}
__device__ __forceinline__ float rcpf(float x) {
    float y; asm("rcp.approx.f32 %0, %1;" : "=f"(y) : "f"(x)); return y;
}
__device__ __forceinline__ void mma8(float c[4], u32 a0, u32 a1, u32 b0) {
    asm volatile("mma.sync.aligned.m16n8k8.row.col.f32.f16.f16.f32 "
        "{%0,%1,%2,%3},{%4,%5},{%6},{%0,%1,%2,%3};"
        : "+f"(c[0]), "+f"(c[1]), "+f"(c[2]), "+f"(c[3])
        : "r"(a0), "r"(a1), "r"(b0));
}
__device__ __forceinline__ void mma16(float c[4], const u32 a[4], u32 b0, u32 b1) {
    asm volatile("mma.sync.aligned.m16n8k16.row.col.f32.f16.f16.f32 "
        "{%0,%1,%2,%3},{%4,%5,%6,%7},{%8,%9},{%0,%1,%2,%3};"
        : "+f"(c[0]), "+f"(c[1]), "+f"(c[2]), "+f"(c[3])
        : "r"(a[0]), "r"(a[1]), "r"(a[2]), "r"(a[3]), "r"(b0), "r"(b1));
}

__global__ void __launch_bounds__(256, 3) lepe_fused_kernel(
    const float* __restrict__ temp,
    const float* __restrict__ conv_w,
    const float* __restrict__ conv_b,
    float* __restrict__ out)
{
    __shared__ __align__(16) char sraw[sizeof(AttnSmem)];
    const int t = threadIdx.x;

    if (blockIdx.x < PRE_CTAS) {
        // ================= prepass shard: (b, tensor, head, rg), 8 rows =================
        PreSmem* S = (PreSmem*)sraw;
        const int blk    = blockIdx.x;
        const int rg     = blk & 15;
        const int head   = (blk >> 4) & 7;
        const int bt     = blk >> 7;          // b*3 + tensor
        const int tensor = bt % 3;
        const int b      = bt / 3;
        const float qsc  = (tensor == 0) ? 0.35355339059327373f * 1.4426950408889634f : 1.0f;

        const float* src = temp + ((size_t)(bt * NC + head * HD)) * HWSZ + (size_t)(rg * 8) * NWID;
        const int rloc = t >> 5, wq = t & 31;

#pragma unroll
        for (int d = 0; d < HD; d++) {
            const float4 v = *(const float4*)(src + (size_t)d * HWSZ + rloc * NWID + 4 * wq);
            const float f[4] = {v.x * qsc, v.y * qsc, v.z * qsc, v.w * qsc};
#pragma unroll
            for (int p = 0; p < 4; p++) {
                const int win    = 2 * wq + (p >> 1);
                const int tokloc = 2 * rloc + (p & 1);       // 0..15
                S->Ss[(tokloc * 8 + d) * PSTR + ((win + tokloc) & 63)] = __float2half_rn(f[p]);
            }
        }
        __syncthreads();

        const size_t base = (size_t)(b * NHEAD + head) * NWIN * (NTOK * HD);
        if (tensor < 2) {
            __half* dst = (tensor == 0) ? Qg : Kg;
#pragma unroll
            for (int cc = 0; cc < 8; cc++) {
                const int i2  = t + 256 * cc;
                const int win = i2 >> 5, q = i2 & 31;
                const int tokloc = q >> 1, j = q & 1;
                const int x   = tokloc * 8 + 4 * j;
                const int off = (win + tokloc) & 63;
                const u32 a0 = __half_as_ushort(S->Ss[(x + 0) * PSTR + off]);
                const u32 a1 = __half_as_ushort(S->Ss[(x + 1) * PSTR + off]);
                const u32 a2 = __half_as_ushort(S->Ss[(x + 2) * PSTR + off]);
                const u32 a3 = __half_as_ushort(S->Ss[(x + 3) * PSTR + off]);
                uint2 val; val.x = a0 | (a1 << 16); val.y = a2 | (a3 << 16);
                *(uint2*)&dst[base + (size_t)win * (NTOK * HD) + (16 * rg + tokloc) * 8 + 4 * j] = val;
            }
        } else {
#pragma unroll
            for (int cc = 0; cc < 8; cc++) {
                const int i2  = t + 256 * cc;
                const int win = i2 >> 5, q = i2 & 31;
                const int d = q >> 2, m = q & 3;
                u32 h[4];
#pragma unroll
                for (int i = 0; i < 4; i++) {
                    const int tok = 4 * m + i;
                    h[i] = __half_as_ushort(S->Ss[(tok * 8 + d) * PSTR + ((win + tok) & 63)]);
                }
                uint2 val; val.x = h[0] | (h[1] << 16); val.y = h[2] | (h[3] << 16);
                *(uint2*)&Vg[base + (size_t)win * (HD * NTOK) + d * NTOK + 16 * rg + 4 * m] = val;
            }
        }
        __threadfence();
        __syncthreads();
        if (t == 0) atomicAdd(&cnt_g[b * NHEAD + head], 1u);
        return;
    }

    // ================= attention CTA: (b, head, window pair) =================
    AttnSmem* S = (AttnSmem*)sraw;
    const int ablk = blockIdx.x - PRE_CTAS;
    const int wp   = ablk & 31;
    const int head = (ablk >> 5) & 7;
    const int b    = ablk >> 8;
    const int bh   = ablk >> 5;
    const int cbase = head * HD;
    __half (*Qsm)[HD] = (__half(*)[HD])S->qo;
    __half (*Osm)[12] = (__half(*)[12])S->qo;

    // ---- wait for this (b,head)'s 48 prepass shards ----
    if (t == 0) {
        volatile unsigned int* c = &cnt_g[bh];
        while (*c < 48u) __nanosleep(64);
    }
    __syncthreads();
    __threadfence();

    // ---- coalesced load of staged Q/K/V ----
    {
        const size_t chnk = ((size_t)bh * NWIN + 2 * wp) * (NTOK * HD);
        const uint4* Qg4 = (const uint4*)(Qg + chnk);
        const uint4* Kg4 = (const uint4*)(Kg + chnk);
        const uint4* Vg4 = (const uint4*)(Vg + chnk);
#pragma unroll
        for (int c = 0; c < 2; c++) {
            const int i = t + 256 * c;          // 0..511
            *(uint4*)&Qsm[i][0] = Qg4[i];
            *(uint4*)&S->Ksm[i][0] = Kg4[i];
            const int w = i >> 8, d = (i >> 5) & 7, t8 = (i & 31) * 8;
            *(uint4*)&S->Vt[w][d][t8] = Vg4[i];
        }
        if (t < HD * 9) ((float*)S->Wc)[t] = conv_w[cbase * 9 + t];
        if (t >= 96 && t < 96 + HD) S->Bc[t - 96] = conv_b[cbase + (t - 96)];
    }
    __syncthreads();

    // ---- consumption bookkeeping: last CTA of this bh resets counters for next replay ----
    if (t == 0) {
        const unsigned int r = atomicAdd(&done_g[bh], 1u);
        if (r == 31u) { cnt_g[bh] = 0u; done_g[bh] = 0u; }
    }

    const int wid = t >> 5, l = t & 31;
    const int w2 = wid >> 2, qb = wid & 3;
    const int qr = l >> 2, jj = l & 3, lc = jj * 2;
    const int tb = w2 * NTOK;

    u32 A[4][2];
#pragma unroll
    for (int mt = 0; mt < 4; mt++) {
        const int q0 = tb + qb * 64 + mt * 16 + qr;
        A[mt][0] = *(const u32*)&Qsm[q0][lc];
        A[mt][1] = *(const u32*)&Qsm[q0 + 8][lc];
    }
    __syncthreads();       // Qsm consumed -> region becomes Osm

    float O[4][4], Ssum[4][4];
#pragma unroll
    for (int mt = 0; mt < 4; mt++)
#pragma unroll
        for (int k = 0; k < 4; k++) { O[mt][k] = 0.0f; Ssum[mt][k] = 0.0f; }

    const u32 H1 = 0x3C003C00u;   // f16x2 {1,1}

    u32 kb0 = *(const u32*)&S->Ksm[tb + qr][lc];
    u32 kb1 = *(const u32*)&S->Ksm[tb + 8 + qr][lc];
    u32 bv0 = *(const u32*)&S->Vt[w2][qr][lc];
    u32 bv1 = *(const u32*)&S->Vt[w2][qr][8 + lc];

#pragma unroll 1
    for (int c = 0; c < 16; c++) {
        u32 nk0, nk1, nv0, nv1;
        if (c < 15) {
            const int key1 = (c + 1) * 16;
            nk0 = *(const u32*)&S->Ksm[tb + key1 + qr][lc];
            nk1 = *(const u32*)&S->Ksm[tb + key1 + 8 + qr][lc];
            nv0 = *(const u32*)&S->Vt[w2][qr][key1 + lc];
            nv1 = *(const u32*)&S->Vt[w2][qr][key1 + 8 + lc];
        }
#pragma unroll
        for (int mt = 0; mt < 4; mt++) {
            float D0[4] = {0, 0, 0, 0}, D1[4] = {0, 0, 0, 0};
            mma8(D0, A[mt][0], A[mt][1], kb0);
            mma8(D1, A[mt][0], A[mt][1], kb1);
            u32 pa[4];
            pa[0] = hex2(cvt2h(D0[0], D0[1]));
            pa[1] = hex2(cvt2h(D0[2], D0[3]));
            pa[2] = hex2(cvt2h(D1[0], D1[1]));
            pa[3] = hex2(cvt2h(D1[2], D1[3]));
            mma16(O[mt], pa, bv0, bv1);     // P @ V
            mma16(Ssum[mt], pa, H1, H1);    // exact f32 row sums
        }
        kb0 = nk0; kb1 = nk1; bv0 = nv0; bv1 = nv1;
    }

    // ---- normalize + stage f16 ----
#pragma unroll
    for (int mt = 0; mt < 4; mt++) {
        const float i0 = rcpf(Ssum[mt][0]);
        const float i1 = rcpf(Ssum[mt][2]);
        const int q0 = tb + qb * 64 + mt * 16 + qr;
        *(__half2*)&Osm[q0][lc]     = __floats2half2_rn(O[mt][0] * i0, O[mt][1] * i0);
        *(__half2*)&Osm[q0 + 8][lc] = __floats2half2_rn(O[mt][2] * i1, O[mt][3] * i1);
    }
    __syncthreads();

    // ---- LePE depthwise 3x3 conv + add + store ----
    {
        const int row = t & 127;
        const int ww2 = t >> 7;
        const int win = wp * 2 + ww2;
        float r0[HD], r1[HD];
#pragma unroll
        for (int d = 0; d < HD; d++) { r0[d] = S->Bc[d]; r1[d] = S->Bc[d]; }
#pragma unroll
        for (int dh = -1; dh <= 1; dh++) {
            const int hh = row + dh;
            if (hh < 0 || hh >= NH) continue;
            const int kkr = (dh + 1) * 3;
#pragma unroll
            for (int d = 0; d < HD; d++) {
                const float v0 = __half2float(S->Vt[ww2][d][2 * hh]);
                const float v1 = __half2float(S->Vt[ww2][d][2 * hh + 1]);
                r0[d] = fmaf(S->Wc[d][kkr + 1], v0, r0[d]);
                r0[d] = fmaf(S->Wc[d][kkr + 2], v1, r0[d]);
                r1[d] = fmaf(S->Wc[d][kkr + 0], v0, r1[d]);
                r1[d] = fmaf(S->Wc[d][kkr + 1], v1, r1[d]);
            }
        }
        const int n0 = ww2 * NTOK + 2 * row;
        const int pix0 = row * NWID + 2 * win;
        float* op0 = out + ((size_t)b * HWSZ + pix0) * NC + cbase;
        float* op1 = op0 + NC;
        float4 a0, a1, c0, c1;
        a0.x = __half2float(Osm[n0][0]) + r0[0];
        a0.y = __half2float(Osm[n0][1]) + r0[1];
        a0.z = __half2float(Osm[n0][2]) + r0[2];
        a0.w = __half2float(Osm[n0][3]) + r0[3];
        a1.x = __half2float(Osm[n0][4]) + r0[4];
        a1.y = __half2float(Osm[n0][5]) + r0[5];
        a1.z = __half2float(Osm[n0][6]) + r0[6];
        a1.w = __half2float(Osm[n0][7]) + r0[7];
        ((float4*)op0)[0] = a0; ((float4*)op0)[1] = a1;
        c0.x = __half2float(Osm[n0 + 1][0]) + r1[0];
        c0.y = __half2float(Osm[n0 + 1][1]) + r1[1];
        c0.z = __half2float(Osm[n0 + 1][2]) + r1[2];
        c0.w = __half2float(Osm[n0 + 1][3]) + r1[3];
        c1.x = __half2float(Osm[n0 + 1][4]) + r1[4];
        c1.y = __half2float(Osm[n0 + 1][5]) + r1[5];
        c1.z = __half2float(Osm[n0 + 1][6]) + r1[6];
        c1.w = __half2float(Osm[n0 + 1][7]) + r1[7];
        ((float4*)op1)[0] = c0; ((float4*)op1)[1] = c1;
    }
}

extern "C" void kernel_launch(void* const* d_in, const int* in_sizes, int n_in,
                              void* d_out, int out_size)
{
    const float* temp = (const float*)d_in[0];
    const float* cw   = (const float*)d_in[1];
    const float* cb   = (const float*)d_in[2];
    float* out        = (float*)d_out;
    lepe_fused_kernel<<<PRE_CTAS + ATT_CTAS, 256>>>(temp, cw, cb, out);
}

// round 16
// speedup vs baseline: 1.4706x; 1.4706x over previous
#include <cuda_runtime.h>
#include <cuda_fp16.h>
#include <cstdint>

#define NB    4
#define NC    64
#define NHEAD 8
#define HD    8
#define NWID  128
#define NH    128
#define HWSZ  (NH*NWID)
#define NWIN  64
#define NTOK  256
#define VPAD  264
#define PSTR  65             // prepass staging: 64 windows + 1 pad

typedef uint32_t u32;

// window-major staging (f16): Qg/Kg = [B][head][win][tok][d], Vg = [B][head][win][d][tok]
__device__ __half Qg[(size_t)NB*NHEAD*NWIN*NTOK*HD];
__device__ __half Kg[(size_t)NB*NHEAD*NWIN*NTOK*HD];
__device__ __half Vg[(size_t)NB*NHEAD*NWIN*HD*NTOK];

__device__ __forceinline__ u32 cvt2h(float lo, float hi) {
    u32 r; asm("cvt.rn.f16x2.f32 %0, %1, %2;" : "=r"(r) : "f"(hi), "f"(lo)); return r;
}
__device__ __forceinline__ u32 hex2(u32 x) {
    u32 r; asm("ex2.approx.f16x2 %0, %1;" : "=r"(r) : "r"(x)); return r;
}
__device__ __forceinline__ float rcpf(float x) {
    float y; asm("rcp.approx.f32 %0, %1;" : "=f"(y) : "f"(x)); return y;
}
__device__ __forceinline__ void mma8(float c[4], u32 a0, u32 a1, u32 b0) {
    asm volatile("mma.sync.aligned.m16n8k8.row.col.f32.f16.f16.f32 "
        "{%0,%1,%2,%3},{%4,%5},{%6},{%0,%1,%2,%3};"
        : "+f"(c[0]), "+f"(c[1]), "+f"(c[2]), "+f"(c[3])
        : "r"(a0), "r"(a1), "r"(b0));
}
__device__ __forceinline__ void mma16(float c[4], const u32 a[4], u32 b0, u32 b1) {
    asm volatile("mma.sync.aligned.m16n8k16.row.col.f32.f16.f16.f32 "
        "{%0,%1,%2,%3},{%4,%5,%6,%7},{%8,%9},{%0,%1,%2,%3};"
        : "+f"(c[0]), "+f"(c[1]), "+f"(c[2]), "+f"(c[3])
        : "r"(a[0]), "r"(a[1]), "r"(a[2]), "r"(a[3]), "r"(b0), "r"(b1));
}

// ============ kernel 1: coalesced transpose (C,H,W) -> window-major f16 ============
// (unchanged from R14 — measured at the LTS/DRAM bandwidth cap)
__global__ void __launch_bounds__(256) prepass_kernel(const float* __restrict__ temp)
{
    __shared__ __half Ss[256 * PSTR];
    const int blk    = blockIdx.x;              // ((b*3+tensor)*8+head)*8+rg
    const int rg     = blk & 7;
    const int head   = (blk >> 3) & 7;
    const int tensor = (blk >> 6) % 3;
    const int b      = (blk >> 6) / 3;
    const int r0     = rg * 16;
    const int t      = threadIdx.x;
    const float qsc  = (tensor == 0) ? 0.35355339059327373f * 1.4426950408889634f : 1.0f;

    const float* src = temp + ((size_t)((b * 3 + tensor) * NC + head * HD)) * HWSZ;

#pragma unroll
    for (int c = 0; c < 16; c++) {
        const int i4   = t + 256 * c;
        const int d    = i4 >> 9;
        const int rloc = (i4 >> 5) & 15;
        const int wq   = i4 & 31;
        const float4 v = *(const float4*)(src + (size_t)d * HWSZ + (r0 + rloc) * NWID + 4 * wq);
        const float f[4] = {v.x * qsc, v.y * qsc, v.z * qsc, v.w * qsc};
#pragma unroll
        for (int p = 0; p < 4; p++) {
            const int win    = 2 * wq + (p >> 1);
            const int tokloc = 2 * rloc + (p & 1);
            const int x = (tensor < 2) ? (tokloc * 8 + d) : (d * 32 + tokloc);
            Ss[x * PSTR + win] = __float2half_rn(f[p]);
        }
    }
    __syncthreads();

    const size_t base = (size_t)(b * NHEAD + head) * NWIN * (NTOK * HD);
    if (tensor < 2) {
        __half* dst = (tensor == 0) ? Qg : Kg;
#pragma unroll
        for (int c = 0; c < 16; c++) {
            const int i2  = t + 256 * c;
            const int win = i2 >> 6;
            const int q   = i2 & 63;
            const int tokloc = q >> 1, j = q & 1;
            const int x = tokloc * 8 + 4 * j;
            const u32 a0 = __half_as_ushort(Ss[(x + 0) * PSTR + win]);
            const u32 a1 = __half_as_ushort(Ss[(x + 1) * PSTR + win]);
            const u32 a2 = __half_as_ushort(Ss[(x + 2) * PSTR + win]);
            const u32 a3 = __half_as_ushort(Ss[(x + 3) * PSTR + win]);
            uint2 val; val.x = a0 | (a1 << 16); val.y = a2 | (a3 << 16);
            *(uint2*)&dst[base + (size_t)win * (NTOK * HD) + (2 * r0 + tokloc) * 8 + 4 * j] = val;
        }
    } else {
#pragma unroll
        for (int c = 0; c < 16; c++) {
            const int i2  = t + 256 * c;
            const int win = i2 >> 6;
            const int q   = i2 & 63;
            const int d = q >> 3, m = q & 7;
            const int x = d * 32 + 4 * m;
            const u32 a0 = __half_as_ushort(Ss[(x + 0) * PSTR + win]);
            const u32 a1 = __half_as_ushort(Ss[(x + 1) * PSTR + win]);
            const u32 a2 = __half_as_ushort(Ss[(x + 2) * PSTR + win]);
            const u32 a3 = __half_as_ushort(Ss[(x + 3) * PSTR + win]);
            uint2 val; val.x = a0 | (a1 << 16); val.y = a2 | (a3 << 16);
            *(uint2*)&Vg[base + (size_t)win * (HD * NTOK) + d * NTOK + 2 * r0 + 4 * m] = val;
        }
    }
}

// ============ kernel 2: flash attention + LePE, one window per CTA ============
__global__ void __launch_bounds__(256, 4) lepe_attn_kernel(
    const float* __restrict__ conv_w,
    const float* __restrict__ conv_b,
    float* __restrict__ out)
{
    const int ablk = blockIdx.x;                // (b*8+head)*64 + win
    const int win  = ablk & 63;
    const int head = (ablk >> 6) & 7;
    const int b    = ablk >> 9;
    const int t    = threadIdx.x;
    const int cbase = head * HD;

    __shared__ __half Ksm[NTOK][HD];                       // 4 KB
    __shared__ __align__(16) char qo_raw[NTOK * 12 * 2];   // 6 KB: Qsm then Osm
    __shared__ __half Vt[HD][VPAD];                        // 4.1 KB
    __shared__ float  Wc[HD][9];
    __shared__ float  Bc[HD];
    __half (*Qsm)[HD] = (__half(*)[HD])qo_raw;
    __half (*Osm)[12] = (__half(*)[12])qo_raw;

    // ---- coalesced load of staged Q/K/V (one uint4 per thread per tensor) ----
    {
        const size_t chnk = ((size_t)(b * NHEAD + head) * NWIN + win) * (NTOK * HD);
        const uint4* Qg4 = (const uint4*)(Qg + chnk);
        const uint4* Kg4 = (const uint4*)(Kg + chnk);
        const uint4* Vg4 = (const uint4*)(Vg + chnk);
        *(uint4*)&Qsm[t][0] = Qg4[t];
        *(uint4*)&Ksm[t][0] = Kg4[t];
        const int d = t >> 5, t8 = (t & 31) * 8;
        *(uint4*)&Vt[d][t8] = Vg4[t];
        if (t < HD * 9) ((float*)Wc)[t] = conv_w[cbase * 9 + t];
        if (t >= 96 && t < 96 + HD) Bc[t - 96] = conv_b[cbase + (t - 96)];
    }
    __syncthreads();

    const int wid = t >> 5, l = t & 31;
    const int qr = l >> 2, jj = l & 3, lc = jj * 2;

    u32 A[2][2];
#pragma unroll
    for (int mt = 0; mt < 2; mt++) {
        const int q0 = wid * 32 + mt * 16 + qr;
        A[mt][0] = *(const u32*)&Qsm[q0][lc];
        A[mt][1] = *(const u32*)&Qsm[q0 + 8][lc];
    }
    __syncthreads();       // Qsm consumed -> region becomes Osm

    float O[2][4], Ssum[2][4];
#pragma unroll
    for (int mt = 0; mt < 2; mt++)
#pragma unroll
        for (int k = 0; k < 4; k++) { O[mt][k] = 0.0f; Ssum[mt][k] = 0.0f; }

    const u32 H1 = 0x3C003C00u;   // f16x2 {1,1}

    // 1-deep software pipeline over the 16 key blocks
    u32 kb0 = *(const u32*)&Ksm[qr][lc];
    u32 kb1 = *(const u32*)&Ksm[8 + qr][lc];
    u32 bv0 = *(const u32*)&Vt[qr][lc];
    u32 bv1 = *(const u32*)&Vt[qr][8 + lc];

#pragma unroll 1
    for (int c = 0; c < 16; c++) {
        u32 nk0, nk1, nv0, nv1;
        if (c < 15) {
            const int key1 = (c + 1) * 16;
            nk0 = *(const u32*)&Ksm[key1 + qr][lc];
            nk1 = *(const u32*)&Ksm[key1 + 8 + qr][lc];
            nv0 = *(const u32*)&Vt[qr][key1 + lc];
            nv1 = *(const u32*)&Vt[qr][key1 + 8 + lc];
        }
#pragma unroll
        for (int mt = 0; mt < 2; mt++) {
            float D0[4] = {0, 0, 0, 0}, D1[4] = {0, 0, 0, 0};
            mma8(D0, A[mt][0], A[mt][1], kb0);
            mma8(D1, A[mt][0], A[mt][1], kb1);
            u32 pa[4];
            pa[0] = hex2(cvt2h(D0[0], D0[1]));
            pa[1] = hex2(cvt2h(D0[2], D0[3]));
            pa[2] = hex2(cvt2h(D1[0], D1[1]));
            pa[3] = hex2(cvt2h(D1[2], D1[3]));
            mma16(O[mt], pa, bv0, bv1);     // P @ V
            mma16(Ssum[mt], pa, H1, H1);    // exact f32 row sums
        }
        kb0 = nk0; kb1 = nk1; bv0 = nv0; bv1 = nv1;
    }

    // ---- normalize + stage f16 ----
#pragma unroll
    for (int mt = 0; mt < 2; mt++) {
        const float i0 = rcpf(Ssum[mt][0]);
        const float i1 = rcpf(Ssum[mt][2]);
        const int q0 = wid * 32 + mt * 16 + qr;
        *(__half2*)&Osm[q0][lc]     = __floats2half2_rn(O[mt][0] * i0, O[mt][1] * i0);
        *(__half2*)&Osm[q0 + 8][lc] = __floats2half2_rn(O[mt][2] * i1, O[mt][3] * i1);
    }
    __syncthreads();

    // ---- LePE depthwise 3x3 conv + add + store (one token per thread) ----
    {
        const int row = t >> 1;
        const int wsp = t & 1;
        float r[HD];
#pragma unroll
        for (int d = 0; d < HD; d++) r[d] = Bc[d];
#pragma unroll
        for (int dh = -1; dh <= 1; dh++) {
            const int hh = row + dh;
            if (hh < 0 || hh >= NH) continue;
            const int kkr = (dh + 1) * 3 + 1 - wsp;   // tap col for ww=0
#pragma unroll
            for (int d = 0; d < HD; d++) {
                const float v0 = __half2float(Vt[d][2 * hh]);
                const float v1 = __half2float(Vt[d][2 * hh + 1]);
                r[d] = fmaf(Wc[d][kkr],     v0, r[d]);
                r[d] = fmaf(Wc[d][kkr + 1], v1, r[d]);
            }
        }
        const int pix = row * NWID + 2 * win + wsp;
        float* op = out + ((size_t)b * HWSZ + pix) * NC + cbase;
        float4 o0, o1;
        o0.x = __half2float(Osm[t][0]) + r[0];
        o0.y = __half2float(Osm[t][1]) + r[1];
        o0.z = __half2float(Osm[t][2]) + r[2];
        o0.w = __half2float(Osm[t][3]) + r[3];
        o1.x = __half2float(Osm[t][4]) + r[4];
        o1.y = __half2float(Osm[t][5]) + r[5];
        o1.z = __half2float(Osm[t][6]) + r[6];
        o1.w = __half2float(Osm[t][7]) + r[7];
        ((float4*)op)[0] = o0;
        ((float4*)op)[1] = o1;
    }
}

extern "C" void kernel_launch(void* const* d_in, const int* in_sizes, int n_in,
                              void* d_out, int out_size)
{
    const float* temp = (const float*)d_in[0];
    const float* cw   = (const float*)d_in[1];
    const float* cb   = (const float*)d_in[2];
    float* out        = (float*)d_out;
    prepass_kernel<<<NB * 3 * NHEAD * 8, 256>>>(temp);
    lepe_attn_kernel<<<NB * NHEAD * NWIN, 256>>>(cw, cb, out);
}